// round 16
// baseline (speedup 1.0000x reference)
#include <cuda_runtime.h>
#include <cuda_bf16.h>
#include <math.h>
#include <stdint.h>

#define HID 2048
#define NH 32
#define NKV 8
#define HD 64
#define SEQ 2048
#define BATCH 2
#define MROWS (BATCH * SEQ)      // 4096
#define QCOLS (NH * HD)          // 2048
#define KVCOLS (NKV * HD)        // 512
#define KDIM 2048
#define QKVN 3072                // fused qkv output width

// ---------------------------------------------------------------------------
// Device-global scratch
// ---------------------------------------------------------------------------
__device__ float g_qkv[(size_t)MROWS * QKVN];   // [row][0:2048 q | 2048:2560 k | 2560:3072 v]

__device__ __nv_bfloat16 g_xh[(size_t)MROWS * HID];
__device__ __nv_bfloat16 g_xl[(size_t)MROWS * HID];
__device__ __nv_bfloat16 g_wqkvt_h[(size_t)QKVN * HID];
__device__ __nv_bfloat16 g_wqkvt_l[(size_t)QKVN * HID];
__device__ __nv_bfloat16 g_wot_h[(size_t)HID * QCOLS];
__device__ __nv_bfloat16 g_wot_l[(size_t)HID * QCOLS];
__device__ __nv_bfloat16 g_oh[(size_t)MROWS * QCOLS];
__device__ __nv_bfloat16 g_ol[(size_t)MROWS * QCOLS];

// bf16 hi/lo q,k,v for tensorized attention
__device__ __nv_bfloat16 g_qh[(size_t)MROWS * QCOLS];
__device__ __nv_bfloat16 g_ql[(size_t)MROWS * QCOLS];
__device__ __nv_bfloat16 g_kh[(size_t)MROWS * KVCOLS];
__device__ __nv_bfloat16 g_kl[(size_t)MROWS * KVCOLS];
__device__ __nv_bfloat16 g_vh[(size_t)MROWS * KVCOLS];
__device__ __nv_bfloat16 g_vl[(size_t)MROWS * KVCOLS];

__device__ __forceinline__ __nv_bfloat16* bf_sel(int s) {
    switch (s) {
        case 0:  return g_xh;      case 1:  return g_xl;
        case 2:  return g_wqkvt_h; case 3:  return g_wqkvt_l;
        case 8:  return g_wot_h;   case 9:  return g_wot_l;
        case 10: return g_oh;      default: return g_ol;
    }
}

// ---------------------------------------------------------------------------
// Portable-PTX helpers
// ---------------------------------------------------------------------------
__device__ __forceinline__ uint32_t smem_u32(const void* p) {
    uint32_t a;
    asm("{ .reg .u64 t; cvta.to.shared.u64 t, %1; cvt.u32.u64 %0, t; }"
        : "=r"(a) : "l"(p));
    return a;
}

#define CP16(dst, src) \
    asm volatile("cp.async.cg.shared.global [%0], [%1], 16;" \
                 :: "r"(dst), "l"(src) : "memory")
#define CP_COMMIT() asm volatile("cp.async.commit_group;" ::: "memory")
#define CP_WAIT1()  asm volatile("cp.async.wait_group 1;" ::: "memory")
#define CP_WAIT0()  asm volatile("cp.async.wait_group 0;" ::: "memory")

__device__ __forceinline__ void ldsm_x4(uint32_t* r, uint32_t addr) {
    asm volatile("ldmatrix.sync.aligned.m8n8.x4.shared.b16 {%0,%1,%2,%3}, [%4];"
                 : "=r"(r[0]), "=r"(r[1]), "=r"(r[2]), "=r"(r[3]) : "r"(addr));
}
__device__ __forceinline__ void ldsm_x4_t(uint32_t* r, uint32_t addr) {
    asm volatile("ldmatrix.sync.aligned.m8n8.x4.trans.shared.b16 {%0,%1,%2,%3}, [%4];"
                 : "=r"(r[0]), "=r"(r[1]), "=r"(r[2]), "=r"(r[3]) : "r"(addr));
}
__device__ __forceinline__ void mma16816(float* c, const uint32_t* a,
                                         const uint32_t* b) {
    asm volatile(
        "mma.sync.aligned.m16n8k16.row.col.f32.bf16.bf16.f32 "
        "{%0,%1,%2,%3}, {%4,%5,%6,%7}, {%8,%9}, {%0,%1,%2,%3};"
        : "+f"(c[0]), "+f"(c[1]), "+f"(c[2]), "+f"(c[3])
        : "r"(a[0]), "r"(a[1]), "r"(a[2]), "r"(a[3]), "r"(b[0]), "r"(b[1]));
}
__device__ __forceinline__ void mma16816_2(float* c, const uint32_t* a,
                                           uint32_t b0, uint32_t b1) {
    uint32_t b[2] = {b0, b1};
    mma16816(c, a, b);
}

// ---------------------------------------------------------------------------
// Prep: split x (fp32) into bf16 hi/lo
// ---------------------------------------------------------------------------
__global__ __launch_bounds__(256) void split_x_k(const float* __restrict__ X) {
    size_t i = ((size_t)blockIdx.x * 256 + threadIdx.x) * 4;
    float4 f = *(const float4*)(X + i);
    __nv_bfloat162 h01 = __floats2bfloat162_rn(f.x, f.y);
    __nv_bfloat162 h23 = __floats2bfloat162_rn(f.z, f.w);
    __nv_bfloat162 l01 = __floats2bfloat162_rn(f.x - __bfloat162float(h01.x),
                                               f.y - __bfloat162float(h01.y));
    __nv_bfloat162 l23 = __floats2bfloat162_rn(f.z - __bfloat162float(h23.x),
                                               f.w - __bfloat162float(h23.y));
    *(uint2*)(g_xh + i) = make_uint2(*(uint32_t*)&h01, *(uint32_t*)&h23);
    *(uint2*)(g_xl + i) = make_uint2(*(uint32_t*)&l01, *(uint32_t*)&l23);
}

// Prep: split v (from fused qkv) into bf16 hi/lo
__global__ __launch_bounds__(256) void split_v_k() {
    size_t j = ((size_t)blockIdx.x * 256 + threadIdx.x) * 4;  // v element idx
    int row = (int)(j >> 9);          // /512
    int col = (int)(j & 511);
    float4 f = *(const float4*)(g_qkv + (size_t)row * QKVN + 2560 + col);
    __nv_bfloat162 h01 = __floats2bfloat162_rn(f.x, f.y);
    __nv_bfloat162 h23 = __floats2bfloat162_rn(f.z, f.w);
    __nv_bfloat162 l01 = __floats2bfloat162_rn(f.x - __bfloat162float(h01.x),
                                               f.y - __bfloat162float(h01.y));
    __nv_bfloat162 l23 = __floats2bfloat162_rn(f.z - __bfloat162float(h23.x),
                                               f.w - __bfloat162float(h23.y));
    *(uint2*)(g_vh + j) = make_uint2(*(uint32_t*)&h01, *(uint32_t*)&h23);
    *(uint2*)(g_vl + j) = make_uint2(*(uint32_t*)&l01, *(uint32_t*)&l23);
}

// ---------------------------------------------------------------------------
// Prep: transpose W [K x N] fp32 -> Wt [rowoff + N x K] bf16 hi/lo
// ---------------------------------------------------------------------------
__global__ __launch_bounds__(256) void transpose_split_k(const float* __restrict__ W,
                                                         int N, int rowoff,
                                                         int dh_sel, int dl_sel) {
    __shared__ float tile[32][33];
    int n0 = blockIdx.x * 32, k0 = blockIdx.y * 32;
    int tx = threadIdx.x & 31, ty = threadIdx.x >> 5;
    for (int r = ty; r < 32; r += 8)
        tile[r][tx] = W[(size_t)(k0 + r) * N + n0 + tx];
    __syncthreads();
    __nv_bfloat16* Dh = bf_sel(dh_sel);
    __nv_bfloat16* Dl = bf_sel(dl_sel);
    for (int r = ty; r < 32; r += 8) {
        float v = tile[tx][r];
        __nv_bfloat16 h = __float2bfloat16(v);
        size_t drow = (size_t)(rowoff + n0 + r);
        Dh[drow * KDIM + k0 + tx] = h;
        Dl[drow * KDIM + k0 + tx] = __float2bfloat16(v - __bfloat162float(h));
    }
}

// ---------------------------------------------------------------------------
// mma.sync bf16x3-split GEMM. R13 base (K-chunk 64, 144B rows, 2-stage
// cp.async); single change: B fragments via one ldmatrix.x4 per n16 pair.
// C[M,N] = A[M,K] @ Bt[N,K]^T  (fp32 out)
// ---------------------------------------------------------------------------
#define ROW_B   144
#define TILE_B  (128 * ROW_B)
#define OFF_AH  0
#define OFF_AL  (TILE_B)
#define OFF_BH  (2 * TILE_B)
#define OFF_BL  (3 * TILE_B)
#define BUF_B   (4 * TILE_B)
#define MM_SMEM (2 * BUF_B)

// EXACT R9/R13 load_chunk: 128 rows x 8 chunks of 16B per tile
__device__ __forceinline__ void load_chunk(
    uint32_t sbase, int buf, const __nv_bfloat16* Ah, const __nv_bfloat16* Al,
    const __nv_bfloat16* Bh, const __nv_bfloat16* Bl,
    int rowBase, int colBase, int k0, int tid) {
    uint32_t sb = sbase + buf * BUF_B;
#pragma unroll
    for (int u = 0; u < 4; u++) {
        int i = tid + 256 * u;
        int r = i >> 3, cc = i & 7;
        uint32_t d = (uint32_t)(r * ROW_B + cc * 16);
        size_t ga = (size_t)(rowBase + r) * KDIM + k0 + cc * 8;
        CP16(sb + OFF_AH + d, Ah + ga);
        CP16(sb + OFF_AL + d, Al + ga);
        size_t gb = (size_t)(colBase + r) * KDIM + k0 + cc * 8;
        CP16(sb + OFF_BH + d, Bh + gb);
        CP16(sb + OFF_BL + d, Bl + gb);
    }
}

__global__ __launch_bounds__(256) void mm_k(int ah_sel, int al_sel, int bh_sel,
                                            int bl_sel, float* __restrict__ Cext,
                                            int csel, int N) {
    extern __shared__ char dsm[];
    const uint32_t sbase = smem_u32(dsm);
    const int tid  = threadIdx.x;
    const int wid  = tid >> 5, lane = tid & 31;
    const int wr   = wid >> 2, wc = wid & 3;
    const int rowBase = blockIdx.y * 128;
    const int colBase = blockIdx.x * 128;

    const __nv_bfloat16* Ah = bf_sel(ah_sel);
    const __nv_bfloat16* Al = bf_sel(al_sel);
    const __nv_bfloat16* Bh = bf_sel(bh_sel);
    const __nv_bfloat16* Bl = bf_sel(bl_sel);

    float acc[4][4][4];
#pragma unroll
    for (int m = 0; m < 4; m++)
#pragma unroll
        for (int n = 0; n < 4; n++)
#pragma unroll
            for (int j = 0; j < 4; j++) acc[m][n][j] = 0.f;

    const uint32_t aRowOff =
        (uint32_t)((wr * 64 + (lane & 15)) * ROW_B + ((lane >> 4) << 4));
    // B via ldmatrix.x4 (R10/R14-proven mapping): rows lane&15, k-half lane>>4
    const uint32_t bRowOff =
        (uint32_t)((wc * 32 + (lane & 15)) * ROW_B + ((lane >> 4) << 4));

    load_chunk(sbase, 0, Ah, Al, Bh, Bl, rowBase, colBase, 0, tid);
    CP_COMMIT();

    const int NC = KDIM / 64;
    int buf = 0;
    for (int c = 0; c < NC; c++) {
        if (c + 1 < NC) {
            load_chunk(sbase, buf ^ 1, Ah, Al, Bh, Bl, rowBase, colBase,
                       (c + 1) * 64, tid);
            CP_COMMIT();
            CP_WAIT1();
        } else {
            CP_WAIT0();
        }
        __syncthreads();

        uint32_t sb = sbase + buf * BUF_B;
#pragma unroll
        for (int ks = 0; ks < 4; ks++) {
            uint32_t kb = ks * 32;
            uint32_t ah[4][4], al[4][4];
#pragma unroll
            for (int m = 0; m < 4; m++) {
                uint32_t ra = sb + OFF_AH + aRowOff + (uint32_t)(m * 16 * ROW_B) + kb;
                ldsm_x4(ah[m], ra);
                ldsm_x4(al[m], ra + (OFF_AL - OFF_AH));
            }
#pragma unroll
            for (int np = 0; np < 2; np++) {
                uint32_t bxh[4], bxl[4];
                uint32_t rb = sb + OFF_BH + bRowOff + (uint32_t)(np * 16 * ROW_B) + kb;
                ldsm_x4(bxh, rb);
                ldsm_x4(bxl, rb + (OFF_BL - OFF_BH));
#pragma unroll
                for (int m = 0; m < 4; m++) {
                    mma16816_2(acc[m][2 * np], ah[m], bxh[0], bxh[2]);
                    mma16816_2(acc[m][2 * np], al[m], bxh[0], bxh[2]);
                    mma16816_2(acc[m][2 * np], ah[m], bxl[0], bxl[2]);
                    mma16816_2(acc[m][2 * np + 1], ah[m], bxh[1], bxh[3]);
                    mma16816_2(acc[m][2 * np + 1], al[m], bxh[1], bxh[3]);
                    mma16816_2(acc[m][2 * np + 1], ah[m], bxl[1], bxl[3]);
                }
            }
        }
        __syncthreads();
        buf ^= 1;
    }

    float* C = (csel == 0) ? g_qkv : Cext;
    const int r0 = rowBase + wr * 64 + (lane >> 2);
    const int c0 = colBase + wc * 32 + ((lane & 3) << 1);
#pragma unroll
    for (int m = 0; m < 4; m++)
#pragma unroll
        for (int n = 0; n < 4; n++) {
            float* p0 = C + (size_t)(r0 + m * 16) * N + c0 + n * 8;
            float* p1 = p0 + 8 * N;
            *(float2*)p0 = make_float2(acc[m][n][0], acc[m][n][1]);
            *(float2*)p1 = make_float2(acc[m][n][2], acc[m][n][3]);
        }
}

// ---------------------------------------------------------------------------
// Fused RMSNorm + RoPE; reads fused qkv, emits bf16 hi/lo (q scaled 0.125)
// ---------------------------------------------------------------------------
__global__ __launch_bounds__(256) void rmsnorm_rope_k(const float* __restrict__ qw,
                                                      const float* __restrict__ kw) {
    const int NQ = MROWS * NH;
    int warp = (blockIdx.x * blockDim.x + threadIdx.x) >> 5;
    int lane = threadIdx.x & 31;

    const float* src;
    const float* w;
    __nv_bfloat16 *dh, *dl;
    int t;
    float scale;
    if (warp < NQ) {
        int row = warp >> 5;
        int h   = warp & 31;
        src = g_qkv + (size_t)row * QKVN + h * HD;
        size_t off = (size_t)row * QCOLS + h * HD;
        dh = g_qh + off; dl = g_ql + off;
        w = qw; t = row & (SEQ - 1); scale = 0.125f;
    } else {
        int vk  = warp - NQ;
        int row = vk >> 3;
        int kvh = vk & 7;
        src = g_qkv + (size_t)row * QKVN + 2048 + kvh * HD;
        size_t off = (size_t)row * KVCOLS + kvh * HD;
        dh = g_kh + off; dl = g_kl + off;
        w = kw; t = row & (SEQ - 1); scale = 1.0f;
    }

    float x1 = src[lane];
    float x2 = src[lane + 32];
    float ss = x1 * x1 + x2 * x2;
#pragma unroll
    for (int o = 16; o; o >>= 1) ss += __shfl_xor_sync(0xffffffffu, ss, o);
    float r = rsqrtf(ss * (1.0f / 64.0f) + 1e-5f);
    float y1 = x1 * r * w[lane];
    float y2 = x2 * r * w[lane + 32];

    float inv = powf(1000000.0f, -(float)lane * (1.0f / 32.0f));
    float ph  = (float)t * inv;
    float s, c;
    sincosf(ph, &s, &c);

    float o1 = (y1 * c - y2 * s) * scale;
    float o2 = (y2 * c + y1 * s) * scale;
    __nv_bfloat16 h1 = __float2bfloat16(o1);
    __nv_bfloat16 h2 = __float2bfloat16(o2);
    dh[lane]      = h1;
    dh[lane + 32] = h2;
    dl[lane]      = __float2bfloat16(o1 - __bfloat162float(h1));
    dl[lane + 32] = __float2bfloat16(o2 - __bfloat162float(h2));
}

// ---------------------------------------------------------------------------
// Tensorized causal flash attention (EXACT R9/R13 version, proven fastest)
// ---------------------------------------------------------------------------
#define PB 144
#define TILE9 (64 * PB)
#define SM_QH 0
#define SM_QL TILE9
#define SM_KV (2 * TILE9)
#define KVBUF (4 * TILE9)
#define ATT_SMEM (2 * TILE9 + 2 * KVBUF)   // 92160

__global__ __launch_bounds__(128) void attn_mma_k() {
    extern __shared__ char dsm[];
    const uint32_t sb = smem_u32(dsm);
    const int tid = threadIdx.x, lane = tid & 31, warp = tid >> 5;
    const int qt = 31 - blockIdx.x;
    const int hb = blockIdx.y;
    const int b = hb >> 5, h = hb & 31, kvh = h >> 2;

    const size_t qoff   = (size_t)(b * SEQ + qt * 64) * QCOLS + h * HD;
    const size_t kvbase = (size_t)(b * SEQ) * KVCOLS + kvh * HD;

#pragma unroll
    for (int u = 0; u < 8; u++) {
        int i = tid + 128 * u;
        int tno = i >> 9, idx = i & 511;
        int r = idx >> 3, c = idx & 7;
        const __nv_bfloat16* src =
            (tno ? g_ql : g_qh) + qoff + (size_t)r * QCOLS + c * 8;
        CP16(sb + (tno ? SM_QL : SM_QH) + r * PB + c * 16, src);
    }
    {
        const __nv_bfloat16* bases[4] = {g_kh + kvbase, g_kl + kvbase,
                                         g_vh + kvbase, g_vl + kvbase};
#pragma unroll
        for (int u = 0; u < 16; u++) {
            int i = tid + 128 * u;
            int tno = i >> 9, idx = i & 511;
            int r = idx >> 3, c = idx & 7;
            CP16(sb + SM_KV + tno * TILE9 + r * PB + c * 16,
                 bases[tno] + (size_t)r * KVCOLS + c * 8);
        }
    }
    CP_COMMIT();

    float oacc[8][4];
#pragma unroll
    for (int nt = 0; nt < 8; nt++)
#pragma unroll
        for (int j = 0; j < 4; j++) oacc[nt][j] = 0.f;
    float l0 = 0.f, l1 = 0.f;
    uint32_t qfh[4][4], qfl[4][4];

    const uint32_t aOff =
        (uint32_t)((warp * 16 + (lane & 15)) * PB + ((lane >> 4) << 4));
    const uint32_t kOff =
        (uint32_t)(((lane & 7) + ((lane >> 4) & 1) * 8) * PB +
                   ((lane >> 3) & 1) * 16);
    const uint32_t vOff =
        (uint32_t)(((lane & 7) + ((lane >> 3) & 1) * 8) * PB +
                   ((lane >> 4) & 1) * 16);

    int bsel = 0;
    for (int kn = 0; kn <= qt; kn++) {
        if (kn < qt) {
            size_t off = kvbase + (size_t)(kn + 1) * 64 * KVCOLS;
            const __nv_bfloat16* bases[4] = {g_kh + off, g_kl + off,
                                             g_vh + off, g_vl + off};
#pragma unroll
            for (int u = 0; u < 16; u++) {
                int i = tid + 128 * u;
                int tno = i >> 9, idx = i & 511;
                int r = idx >> 3, c = idx & 7;
                CP16(sb + SM_KV + (bsel ^ 1) * KVBUF + tno * TILE9 + r * PB + c * 16,
                     bases[tno] + (size_t)r * KVCOLS + c * 8);
            }
            CP_COMMIT();
            CP_WAIT1();
        } else {
            CP_WAIT0();
        }
        __syncthreads();

        if (kn == 0) {
#pragma unroll
            for (int ks = 0; ks < 4; ks++) {
                ldsm_x4(qfh[ks], sb + SM_QH + aOff + ks * 32);
                ldsm_x4(qfl[ks], sb + SM_QL + aOff + ks * 32);
            }
        }

        const uint32_t kb = sb + SM_KV + bsel * KVBUF;

        float sacc[8][4];
#pragma unroll
        for (int nt = 0; nt < 8; nt++)
#pragma unroll
            for (int j = 0; j < 4; j++) sacc[nt][j] = 0.f;
#pragma unroll
        for (int ks = 0; ks < 4; ks++) {
#pragma unroll
            for (int u = 0; u < 4; u++) {
                uint32_t kfh[4], kfl[4];
                uint32_t addr = kb + kOff + (uint32_t)(u * 16 * PB) + ks * 32;
                ldsm_x4(kfh, addr);
                ldsm_x4(kfl, addr + TILE9);
                mma16816(sacc[2 * u], qfh[ks], kfh);
                mma16816(sacc[2 * u], qfl[ks], kfh);
                mma16816(sacc[2 * u], qfh[ks], kfl);
                mma16816(sacc[2 * u + 1], qfh[ks], kfh + 2);
                mma16816(sacc[2 * u + 1], qfl[ks], kfh + 2);
                mma16816(sacc[2 * u + 1], qfh[ks], kfl + 2);
            }
        }

        const int row0 = warp * 16 + (lane >> 2);
        if (kn == qt) {
#pragma unroll
            for (int nt = 0; nt < 8; nt++) {
                int c0 = nt * 8 + 2 * (lane & 3);
                float p0 = (c0     <= row0)     ? __expf(sacc[nt][0]) : 0.f;
                float p1 = (c0 + 1 <= row0)     ? __expf(sacc[nt][1]) : 0.f;
                float p2 = (c0     <= row0 + 8) ? __expf(sacc[nt][2]) : 0.f;
                float p3 = (c0 + 1 <= row0 + 8) ? __expf(sacc[nt][3]) : 0.f;
                l0 += p0 + p1; l1 += p2 + p3;
                sacc[nt][0] = p0; sacc[nt][1] = p1;
                sacc[nt][2] = p2; sacc[nt][3] = p3;
            }
        } else {
#pragma unroll
            for (int nt = 0; nt < 8; nt++) {
                float p0 = __expf(sacc[nt][0]);
                float p1 = __expf(sacc[nt][1]);
                float p2 = __expf(sacc[nt][2]);
                float p3 = __expf(sacc[nt][3]);
                l0 += p0 + p1; l1 += p2 + p3;
                sacc[nt][0] = p0; sacc[nt][1] = p1;
                sacc[nt][2] = p2; sacc[nt][3] = p3;
            }
        }

        uint32_t pha[4][4], pla[4][4];
#pragma unroll
        for (int ks = 0; ks < 4; ks++) {
            const float* sA = sacc[2 * ks];
            const float* sB = sacc[2 * ks + 1];
            __nv_bfloat162 h0 = __floats2bfloat162_rn(sA[0], sA[1]);
            __nv_bfloat162 h1 = __floats2bfloat162_rn(sA[2], sA[3]);
            __nv_bfloat162 h2 = __floats2bfloat162_rn(sB[0], sB[1]);
            __nv_bfloat162 h3 = __floats2bfloat162_rn(sB[2], sB[3]);
            pha[ks][0] = *(uint32_t*)&h0; pha[ks][1] = *(uint32_t*)&h1;
            pha[ks][2] = *(uint32_t*)&h2; pha[ks][3] = *(uint32_t*)&h3;
            __nv_bfloat162 e0 = __floats2bfloat162_rn(
                sA[0] - __bfloat162float(h0.x), sA[1] - __bfloat162float(h0.y));
            __nv_bfloat162 e1 = __floats2bfloat162_rn(
                sA[2] - __bfloat162float(h1.x), sA[3] - __bfloat162float(h1.y));
            __nv_bfloat162 e2 = __floats2bfloat162_rn(
                sB[0] - __bfloat162float(h2.x), sB[1] - __bfloat162float(h2.y));
            __nv_bfloat162 e3 = __floats2bfloat162_rn(
                sB[2] - __bfloat162float(h3.x), sB[3] - __bfloat162float(h3.y));
            pla[ks][0] = *(uint32_t*)&e0; pla[ks][1] = *(uint32_t*)&e1;
            pla[ks][2] = *(uint32_t*)&e2; pla[ks][3] = *(uint32_t*)&e3;
        }

        const uint32_t vb = kb + 2 * TILE9;
#pragma unroll
        for (int ks = 0; ks < 4; ks++) {
#pragma unroll
            for (int jp = 0; jp < 4; jp++) {
                uint32_t vfh[4], vfl[4];
                uint32_t addr = vb + vOff + (uint32_t)(ks * 16 * PB) + jp * 32;
                ldsm_x4_t(vfh, addr);
                ldsm_x4_t(vfl, addr + TILE9);
                mma16816(oacc[2 * jp], pha[ks], vfh);
                mma16816(oacc[2 * jp], pla[ks], vfh);
                mma16816(oacc[2 * jp], pha[ks], vfl);
                mma16816(oacc[2 * jp + 1], pha[ks], vfh + 2);
                mma16816(oacc[2 * jp + 1], pla[ks], vfh + 2);
                mma16816(oacc[2 * jp + 1], pha[ks], vfl + 2);
            }
        }
        __syncthreads();
        bsel ^= 1;
    }

    l0 += __shfl_xor_sync(0xffffffffu, l0, 1);
    l0 += __shfl_xor_sync(0xffffffffu, l0, 2);
    l1 += __shfl_xor_sync(0xffffffffu, l1, 1);
    l1 += __shfl_xor_sync(0xffffffffu, l1, 2);
    float i0 = 1.0f / l0, i1 = 1.0f / l1;

    size_t rg0 = (size_t)(b * SEQ + qt * 64 + warp * 16 + (lane >> 2));
    int colb = h * HD + 2 * (lane & 3);
#pragma unroll
    for (int nt = 0; nt < 8; nt++) {
        float a0 = oacc[nt][0] * i0, a1 = oacc[nt][1] * i0;
        float a2 = oacc[nt][2] * i1, a3 = oacc[nt][3] * i1;
        __nv_bfloat162 H0 = __floats2bfloat162_rn(a0, a1);
        __nv_bfloat162 H1 = __floats2bfloat162_rn(a2, a3);
        __nv_bfloat162 L0 = __floats2bfloat162_rn(a0 - __bfloat162float(H0.x),
                                                  a1 - __bfloat162float(H0.y));
        __nv_bfloat162 L1 = __floats2bfloat162_rn(a2 - __bfloat162float(H1.x),
                                                  a3 - __bfloat162float(H1.y));
        size_t off0 = rg0 * QCOLS + colb + nt * 8;
        size_t off1 = (rg0 + 8) * QCOLS + colb + nt * 8;
        *(uint32_t*)(g_oh + off0) = *(uint32_t*)&H0;
        *(uint32_t*)(g_ol + off0) = *(uint32_t*)&L0;
        *(uint32_t*)(g_oh + off1) = *(uint32_t*)&H1;
        *(uint32_t*)(g_ol + off1) = *(uint32_t*)&L1;
    }
}

// ---------------------------------------------------------------------------
extern "C" void kernel_launch(void* const* d_in, const int* in_sizes, int n_in,
                              void* d_out, int out_size) {
    const float* x  = (const float*)d_in[0];
    const float* Wq = (const float*)d_in[1];
    const float* Wk = (const float*)d_in[2];
    const float* Wv = (const float*)d_in[3];
    const float* Wo = (const float*)d_in[4];
    const float* qw = (const float*)d_in[5];
    const float* kw = (const float*)d_in[6];
    float* out = (float*)d_out;

    static int attr_set = 0;
    if (!attr_set) {
        cudaFuncSetAttribute(mm_k, cudaFuncAttributeMaxDynamicSharedMemorySize,
                             MM_SMEM);
        cudaFuncSetAttribute(attn_mma_k,
                             cudaFuncAttributeMaxDynamicSharedMemorySize,
                             ATT_SMEM);
        attr_set = 1;
    }

    // Prep (reordered so QKV mm_k lands in ncu's capture slot):
    // launches 1-4: split_x + QKV transposes; launch 5: mm_k (QKV)
    split_x_k<<<(MROWS * HID) / (256 * 4), 256>>>(x);
    transpose_split_k<<<dim3(QCOLS / 32, HID / 32), 256>>>(Wq, QCOLS, 0, 2, 3);
    transpose_split_k<<<dim3(KVCOLS / 32, HID / 32), 256>>>(Wk, KVCOLS, 2048, 2, 3);
    transpose_split_k<<<dim3(KVCOLS / 32, HID / 32), 256>>>(Wv, KVCOLS, 2560, 2, 3);

    // Fused QKV projection (one GEMM, N=3072)
    mm_k<<<dim3(QKVN / 128, MROWS / 128), 256, MM_SMEM>>>(0, 1, 2, 3,
                                                          nullptr, 0, QKVN);

    // Wo transpose (only needed before the final GEMM)
    transpose_split_k<<<dim3(QCOLS / 32, HID / 32), 256>>>(Wo, QCOLS, 0, 8, 9);

    // RMSNorm + RoPE -> bf16 hi/lo q,k ; split v from fused buffer
    {
        int nwarps = MROWS * NH + MROWS * NKV;
        rmsnorm_rope_k<<<nwarps / 8, 256>>>(qw, kw);
    }
    split_v_k<<<(MROWS * KVCOLS) / (256 * 4), 256>>>();

    // Tensorized causal GQA flash attention -> g_oh / g_ol
    attn_mma_k<<<dim3(SEQ / 64, BATCH * NH), 128, ATT_SMEM>>>();

    // Output projection
    mm_k<<<dim3(QCOLS / 128, MROWS / 128), 256, MM_SMEM>>>(10, 11, 8, 9,
                                                           out, 99, QCOLS);
}

// round 17
// speedup vs baseline: 1.1212x; 1.1212x over previous
#include <cuda_runtime.h>
#include <cuda_bf16.h>
#include <math.h>
#include <stdint.h>

#define HID 2048
#define NH 32
#define NKV 8
#define HD 64
#define SEQ 2048
#define BATCH 2
#define MROWS (BATCH * SEQ)      // 4096
#define QCOLS (NH * HD)          // 2048
#define KVCOLS (NKV * HD)        // 512
#define KDIM 2048
#define QKVN 3072                // fused qkv output width

// ---------------------------------------------------------------------------
// Device-global scratch
// ---------------------------------------------------------------------------
__device__ float g_qkv[(size_t)MROWS * QKVN];   // [row][0:2048 q | 2048:2560 k | 2560:3072 v(f32 unused)]

__device__ __nv_bfloat16 g_xh[(size_t)MROWS * HID];
__device__ __nv_bfloat16 g_xl[(size_t)MROWS * HID];
__device__ __nv_bfloat16 g_wqkvt_h[(size_t)QKVN * HID];
__device__ __nv_bfloat16 g_wqkvt_l[(size_t)QKVN * HID];
__device__ __nv_bfloat16 g_wot_h[(size_t)HID * QCOLS];
__device__ __nv_bfloat16 g_wot_l[(size_t)HID * QCOLS];
__device__ __nv_bfloat16 g_oh[(size_t)MROWS * QCOLS];
__device__ __nv_bfloat16 g_ol[(size_t)MROWS * QCOLS];

// bf16 hi/lo q,k,v for tensorized attention
__device__ __nv_bfloat16 g_qh[(size_t)MROWS * QCOLS];
__device__ __nv_bfloat16 g_ql[(size_t)MROWS * QCOLS];
__device__ __nv_bfloat16 g_kh[(size_t)MROWS * KVCOLS];
__device__ __nv_bfloat16 g_kl[(size_t)MROWS * KVCOLS];
__device__ __nv_bfloat16 g_vh[(size_t)MROWS * KVCOLS];
__device__ __nv_bfloat16 g_vl[(size_t)MROWS * KVCOLS];

__device__ __forceinline__ __nv_bfloat16* bf_sel(int s) {
    switch (s) {
        case 0:  return g_xh;      case 1:  return g_xl;
        case 2:  return g_wqkvt_h; case 3:  return g_wqkvt_l;
        case 8:  return g_wot_h;   case 9:  return g_wot_l;
        case 10: return g_oh;      default: return g_ol;
    }
}

// ---------------------------------------------------------------------------
// Portable-PTX helpers
// ---------------------------------------------------------------------------
__device__ __forceinline__ uint32_t smem_u32(const void* p) {
    uint32_t a;
    asm("{ .reg .u64 t; cvta.to.shared.u64 t, %1; cvt.u32.u64 %0, t; }"
        : "=r"(a) : "l"(p));
    return a;
}

#define CP16(dst, src) \
    asm volatile("cp.async.cg.shared.global [%0], [%1], 16;" \
                 :: "r"(dst), "l"(src) : "memory")
#define CP_COMMIT() asm volatile("cp.async.commit_group;" ::: "memory")
#define CP_WAIT1()  asm volatile("cp.async.wait_group 1;" ::: "memory")
#define CP_WAIT0()  asm volatile("cp.async.wait_group 0;" ::: "memory")

__device__ __forceinline__ void ldsm_x4(uint32_t* r, uint32_t addr) {
    asm volatile("ldmatrix.sync.aligned.m8n8.x4.shared.b16 {%0,%1,%2,%3}, [%4];"
                 : "=r"(r[0]), "=r"(r[1]), "=r"(r[2]), "=r"(r[3]) : "r"(addr));
}
__device__ __forceinline__ void ldsm_x4_t(uint32_t* r, uint32_t addr) {
    asm volatile("ldmatrix.sync.aligned.m8n8.x4.trans.shared.b16 {%0,%1,%2,%3}, [%4];"
                 : "=r"(r[0]), "=r"(r[1]), "=r"(r[2]), "=r"(r[3]) : "r"(addr));
}
__device__ __forceinline__ void ldsm_x2(uint32_t* r, uint32_t addr) {
    asm volatile("ldmatrix.sync.aligned.m8n8.x2.shared.b16 {%0,%1}, [%2];"
                 : "=r"(r[0]), "=r"(r[1]) : "r"(addr));
}
__device__ __forceinline__ void mma16816(float* c, const uint32_t* a,
                                         const uint32_t* b) {
    asm volatile(
        "mma.sync.aligned.m16n8k16.row.col.f32.bf16.bf16.f32 "
        "{%0,%1,%2,%3}, {%4,%5,%6,%7}, {%8,%9}, {%0,%1,%2,%3};"
        : "+f"(c[0]), "+f"(c[1]), "+f"(c[2]), "+f"(c[3])
        : "r"(a[0]), "r"(a[1]), "r"(a[2]), "r"(a[3]), "r"(b[0]), "r"(b[1]));
}

// ---------------------------------------------------------------------------
// Prep: split x (fp32) into bf16 hi/lo
// ---------------------------------------------------------------------------
__global__ __launch_bounds__(256) void split_x_k(const float* __restrict__ X) {
    size_t i = ((size_t)blockIdx.x * 256 + threadIdx.x) * 4;
    float4 f = *(const float4*)(X + i);
    __nv_bfloat162 h01 = __floats2bfloat162_rn(f.x, f.y);
    __nv_bfloat162 h23 = __floats2bfloat162_rn(f.z, f.w);
    __nv_bfloat162 l01 = __floats2bfloat162_rn(f.x - __bfloat162float(h01.x),
                                               f.y - __bfloat162float(h01.y));
    __nv_bfloat162 l23 = __floats2bfloat162_rn(f.z - __bfloat162float(h23.x),
                                               f.w - __bfloat162float(h23.y));
    *(uint2*)(g_xh + i) = make_uint2(*(uint32_t*)&h01, *(uint32_t*)&h23);
    *(uint2*)(g_xl + i) = make_uint2(*(uint32_t*)&l01, *(uint32_t*)&l23);
}

// ---------------------------------------------------------------------------
// Prep: transpose W [K x N] fp32 -> Wt [rowoff + N x K] bf16 hi/lo
// ---------------------------------------------------------------------------
__global__ __launch_bounds__(256) void transpose_split_k(const float* __restrict__ W,
                                                         int N, int rowoff,
                                                         int dh_sel, int dl_sel) {
    __shared__ float tile[32][33];
    int n0 = blockIdx.x * 32, k0 = blockIdx.y * 32;
    int tx = threadIdx.x & 31, ty = threadIdx.x >> 5;
    for (int r = ty; r < 32; r += 8)
        tile[r][tx] = W[(size_t)(k0 + r) * N + n0 + tx];
    __syncthreads();
    __nv_bfloat16* Dh = bf_sel(dh_sel);
    __nv_bfloat16* Dl = bf_sel(dl_sel);
    for (int r = ty; r < 32; r += 8) {
        float v = tile[tx][r];
        __nv_bfloat16 h = __float2bfloat16(v);
        size_t drow = (size_t)(rowoff + n0 + r);
        Dh[drow * KDIM + k0 + tx] = h;
        Dl[drow * KDIM + k0 + tx] = __float2bfloat16(v - __bfloat162float(h));
    }
}

// ---------------------------------------------------------------------------
// mma.sync bf16x3-split GEMM (EXACT R13 mainloop: K-chunk 64, 144B rows,
// 2-stage cp.async, ldsm_x2 B-frags). Epilogue: V-region tiles (csel==0 &&
// colBase>=2560) emit bf16 hi/lo directly to g_vh/g_vl (fused split_v).
// ---------------------------------------------------------------------------
#define ROW_B   144
#define TILE_B  (128 * ROW_B)
#define OFF_AH  0
#define OFF_AL  (TILE_B)
#define OFF_BH  (2 * TILE_B)
#define OFF_BL  (3 * TILE_B)
#define BUF_B   (4 * TILE_B)
#define MM_SMEM (2 * BUF_B)

__device__ __forceinline__ void load_chunk(
    uint32_t sbase, int buf, const __nv_bfloat16* Ah, const __nv_bfloat16* Al,
    const __nv_bfloat16* Bh, const __nv_bfloat16* Bl,
    int rowBase, int colBase, int k0, int tid) {
    uint32_t sb = sbase + buf * BUF_B;
#pragma unroll
    for (int u = 0; u < 4; u++) {
        int i = tid + 256 * u;
        int r = i >> 3, cc = i & 7;
        uint32_t d = (uint32_t)(r * ROW_B + cc * 16);
        size_t ga = (size_t)(rowBase + r) * KDIM + k0 + cc * 8;
        CP16(sb + OFF_AH + d, Ah + ga);
        CP16(sb + OFF_AL + d, Al + ga);
        size_t gb = (size_t)(colBase + r) * KDIM + k0 + cc * 8;
        CP16(sb + OFF_BH + d, Bh + gb);
        CP16(sb + OFF_BL + d, Bl + gb);
    }
}

__global__ __launch_bounds__(256) void mm_k(int ah_sel, int al_sel, int bh_sel,
                                            int bl_sel, float* __restrict__ Cext,
                                            int csel, int N) {
    extern __shared__ char dsm[];
    const uint32_t sbase = smem_u32(dsm);
    const int tid  = threadIdx.x;
    const int wid  = tid >> 5, lane = tid & 31;
    const int wr   = wid >> 2, wc = wid & 3;
    const int rowBase = blockIdx.y * 128;
    const int colBase = blockIdx.x * 128;

    const __nv_bfloat16* Ah = bf_sel(ah_sel);
    const __nv_bfloat16* Al = bf_sel(al_sel);
    const __nv_bfloat16* Bh = bf_sel(bh_sel);
    const __nv_bfloat16* Bl = bf_sel(bl_sel);

    float acc[4][4][4];
#pragma unroll
    for (int m = 0; m < 4; m++)
#pragma unroll
        for (int n = 0; n < 4; n++)
#pragma unroll
            for (int j = 0; j < 4; j++) acc[m][n][j] = 0.f;

    const uint32_t aRowOff =
        (uint32_t)((wr * 64 + (lane & 15)) * ROW_B + ((lane >> 4) << 4));
    const uint32_t bRowOff =
        (uint32_t)((wc * 32 + (lane & 7)) * ROW_B + (((lane >> 3) & 1) << 4));

    load_chunk(sbase, 0, Ah, Al, Bh, Bl, rowBase, colBase, 0, tid);
    CP_COMMIT();

    const int NC = KDIM / 64;
    int buf = 0;
    for (int c = 0; c < NC; c++) {
        if (c + 1 < NC) {
            load_chunk(sbase, buf ^ 1, Ah, Al, Bh, Bl, rowBase, colBase,
                       (c + 1) * 64, tid);
            CP_COMMIT();
            CP_WAIT1();
        } else {
            CP_WAIT0();
        }
        __syncthreads();

        uint32_t sb = sbase + buf * BUF_B;
#pragma unroll
        for (int ks = 0; ks < 4; ks++) {
            uint32_t kb = ks * 32;
            uint32_t ah[4][4], al[4][4];
#pragma unroll
            for (int m = 0; m < 4; m++) {
                uint32_t ra = sb + OFF_AH + aRowOff + (uint32_t)(m * 16 * ROW_B) + kb;
                ldsm_x4(ah[m], ra);
                ldsm_x4(al[m], ra + (OFF_AL - OFF_AH));
            }
            uint32_t bh[4][2], bl[4][2];
#pragma unroll
            for (int n = 0; n < 4; n++) {
                uint32_t rb = sb + OFF_BH + bRowOff + (uint32_t)(n * 8 * ROW_B) + kb;
                ldsm_x2(bh[n], rb);
                ldsm_x2(bl[n], rb + (OFF_BL - OFF_BH));
            }
#pragma unroll
            for (int m = 0; m < 4; m++)
#pragma unroll
                for (int n = 0; n < 4; n++) {
                    mma16816(acc[m][n], ah[m], bh[n]);
                    mma16816(acc[m][n], al[m], bh[n]);
                    mma16816(acc[m][n], ah[m], bl[n]);
                }
        }
        __syncthreads();
        buf ^= 1;
    }

    const int r0 = rowBase + wr * 64 + (lane >> 2);
    const int c0 = colBase + wc * 32 + ((lane & 3) << 1);

    if (csel == 0 && colBase >= 2560) {
        // V region: emit bf16 hi/lo directly (fused split_v; same fp32 values)
#pragma unroll
        for (int m = 0; m < 4; m++)
#pragma unroll
            for (int n = 0; n < 4; n++) {
                int vc = c0 + n * 8 - 2560;
                size_t o0 = (size_t)(r0 + m * 16) * KVCOLS + vc;
                size_t o1 = (size_t)(r0 + m * 16 + 8) * KVCOLS + vc;
                float a0 = acc[m][n][0], a1 = acc[m][n][1];
                float a2 = acc[m][n][2], a3 = acc[m][n][3];
                __nv_bfloat162 H0 = __floats2bfloat162_rn(a0, a1);
                __nv_bfloat162 H1 = __floats2bfloat162_rn(a2, a3);
                __nv_bfloat162 L0 = __floats2bfloat162_rn(
                    a0 - __bfloat162float(H0.x), a1 - __bfloat162float(H0.y));
                __nv_bfloat162 L1 = __floats2bfloat162_rn(
                    a2 - __bfloat162float(H1.x), a3 - __bfloat162float(H1.y));
                *(uint32_t*)(g_vh + o0) = *(uint32_t*)&H0;
                *(uint32_t*)(g_vl + o0) = *(uint32_t*)&L0;
                *(uint32_t*)(g_vh + o1) = *(uint32_t*)&H1;
                *(uint32_t*)(g_vl + o1) = *(uint32_t*)&L1;
            }
    } else {
        float* C = (csel == 0) ? g_qkv : Cext;
#pragma unroll
        for (int m = 0; m < 4; m++)
#pragma unroll
            for (int n = 0; n < 4; n++) {
                float* p0 = C + (size_t)(r0 + m * 16) * N + c0 + n * 8;
                float* p1 = p0 + 8 * N;
                *(float2*)p0 = make_float2(acc[m][n][0], acc[m][n][1]);
                *(float2*)p1 = make_float2(acc[m][n][2], acc[m][n][3]);
            }
    }
}

// ---------------------------------------------------------------------------
// Fused RMSNorm + RoPE; reads fused qkv, emits bf16 hi/lo (q scaled 0.125)
// ---------------------------------------------------------------------------
__global__ __launch_bounds__(256) void rmsnorm_rope_k(const float* __restrict__ qw,
                                                      const float* __restrict__ kw) {
    const int NQ = MROWS * NH;
    int warp = (blockIdx.x * blockDim.x + threadIdx.x) >> 5;
    int lane = threadIdx.x & 31;

    const float* src;
    const float* w;
    __nv_bfloat16 *dh, *dl;
    int t;
    float scale;
    if (warp < NQ) {
        int row = warp >> 5;
        int h   = warp & 31;
        src = g_qkv + (size_t)row * QKVN + h * HD;
        size_t off = (size_t)row * QCOLS + h * HD;
        dh = g_qh + off; dl = g_ql + off;
        w = qw; t = row & (SEQ - 1); scale = 0.125f;
    } else {
        int vk  = warp - NQ;
        int row = vk >> 3;
        int kvh = vk & 7;
        src = g_qkv + (size_t)row * QKVN + 2048 + kvh * HD;
        size_t off = (size_t)row * KVCOLS + kvh * HD;
        dh = g_kh + off; dl = g_kl + off;
        w = kw; t = row & (SEQ - 1); scale = 1.0f;
    }

    float x1 = src[lane];
    float x2 = src[lane + 32];
    float ss = x1 * x1 + x2 * x2;
#pragma unroll
    for (int o = 16; o; o >>= 1) ss += __shfl_xor_sync(0xffffffffu, ss, o);
    float r = rsqrtf(ss * (1.0f / 64.0f) + 1e-5f);
    float y1 = x1 * r * w[lane];
    float y2 = x2 * r * w[lane + 32];

    float inv = powf(1000000.0f, -(float)lane * (1.0f / 32.0f));
    float ph  = (float)t * inv;
    float s, c;
    sincosf(ph, &s, &c);

    float o1 = (y1 * c - y2 * s) * scale;
    float o2 = (y2 * c + y1 * s) * scale;
    __nv_bfloat16 h1 = __float2bfloat16(o1);
    __nv_bfloat16 h2 = __float2bfloat16(o2);
    dh[lane]      = h1;
    dh[lane + 32] = h2;
    dl[lane]      = __float2bfloat16(o1 - __bfloat162float(h1));
    dl[lane + 32] = __float2bfloat16(o2 - __bfloat162float(h2));
}

// ---------------------------------------------------------------------------
// Tensorized causal flash attention (EXACT R9/R13 version, proven fastest)
// ---------------------------------------------------------------------------
#define PB 144
#define TILE9 (64 * PB)
#define SM_QH 0
#define SM_QL TILE9
#define SM_KV (2 * TILE9)
#define KVBUF (4 * TILE9)
#define ATT_SMEM (2 * TILE9 + 2 * KVBUF)   // 92160

__global__ __launch_bounds__(128) void attn_mma_k() {
    extern __shared__ char dsm[];
    const uint32_t sb = smem_u32(dsm);
    const int tid = threadIdx.x, lane = tid & 31, warp = tid >> 5;
    const int qt = 31 - blockIdx.x;
    const int hb = blockIdx.y;
    const int b = hb >> 5, h = hb & 31, kvh = h >> 2;

    const size_t qoff   = (size_t)(b * SEQ + qt * 64) * QCOLS + h * HD;
    const size_t kvbase = (size_t)(b * SEQ) * KVCOLS + kvh * HD;

#pragma unroll
    for (int u = 0; u < 8; u++) {
        int i = tid + 128 * u;
        int tno = i >> 9, idx = i & 511;
        int r = idx >> 3, c = idx & 7;
        const __nv_bfloat16* src =
            (tno ? g_ql : g_qh) + qoff + (size_t)r * QCOLS + c * 8;
        CP16(sb + (tno ? SM_QL : SM_QH) + r * PB + c * 16, src);
    }
    {
        const __nv_bfloat16* bases[4] = {g_kh + kvbase, g_kl + kvbase,
                                         g_vh + kvbase, g_vl + kvbase};
#pragma unroll
        for (int u = 0; u < 16; u++) {
            int i = tid + 128 * u;
            int tno = i >> 9, idx = i & 511;
            int r = idx >> 3, c = idx & 7;
            CP16(sb + SM_KV + tno * TILE9 + r * PB + c * 16,
                 bases[tno] + (size_t)r * KVCOLS + c * 8);
        }
    }
    CP_COMMIT();

    float oacc[8][4];
#pragma unroll
    for (int nt = 0; nt < 8; nt++)
#pragma unroll
        for (int j = 0; j < 4; j++) oacc[nt][j] = 0.f;
    float l0 = 0.f, l1 = 0.f;
    uint32_t qfh[4][4], qfl[4][4];

    const uint32_t aOff =
        (uint32_t)((warp * 16 + (lane & 15)) * PB + ((lane >> 4) << 4));
    const uint32_t kOff =
        (uint32_t)(((lane & 7) + ((lane >> 4) & 1) * 8) * PB +
                   ((lane >> 3) & 1) * 16);
    const uint32_t vOff =
        (uint32_t)(((lane & 7) + ((lane >> 3) & 1) * 8) * PB +
                   ((lane >> 4) & 1) * 16);

    int bsel = 0;
    for (int kn = 0; kn <= qt; kn++) {
        if (kn < qt) {
            size_t off = kvbase + (size_t)(kn + 1) * 64 * KVCOLS;
            const __nv_bfloat16* bases[4] = {g_kh + off, g_kl + off,
                                             g_vh + off, g_vl + off};
#pragma unroll
            for (int u = 0; u < 16; u++) {
                int i = tid + 128 * u;
                int tno = i >> 9, idx = i & 511;
                int r = idx >> 3, c = idx & 7;
                CP16(sb + SM_KV + (bsel ^ 1) * KVBUF + tno * TILE9 + r * PB + c * 16,
                     bases[tno] + (size_t)r * KVCOLS + c * 8);
            }
            CP_COMMIT();
            CP_WAIT1();
        } else {
            CP_WAIT0();
        }
        __syncthreads();

        if (kn == 0) {
#pragma unroll
            for (int ks = 0; ks < 4; ks++) {
                ldsm_x4(qfh[ks], sb + SM_QH + aOff + ks * 32);
                ldsm_x4(qfl[ks], sb + SM_QL + aOff + ks * 32);
            }
        }

        const uint32_t kb = sb + SM_KV + bsel * KVBUF;

        float sacc[8][4];
#pragma unroll
        for (int nt = 0; nt < 8; nt++)
#pragma unroll
            for (int j = 0; j < 4; j++) sacc[nt][j] = 0.f;
#pragma unroll
        for (int ks = 0; ks < 4; ks++) {
#pragma unroll
            for (int u = 0; u < 4; u++) {
                uint32_t kfh[4], kfl[4];
                uint32_t addr = kb + kOff + (uint32_t)(u * 16 * PB) + ks * 32;
                ldsm_x4(kfh, addr);
                ldsm_x4(kfl, addr + TILE9);
                mma16816(sacc[2 * u], qfh[ks], kfh);
                mma16816(sacc[2 * u], qfl[ks], kfh);
                mma16816(sacc[2 * u], qfh[ks], kfl);
                mma16816(sacc[2 * u + 1], qfh[ks], kfh + 2);
                mma16816(sacc[2 * u + 1], qfl[ks], kfh + 2);
                mma16816(sacc[2 * u + 1], qfh[ks], kfl + 2);
            }
        }

        const int row0 = warp * 16 + (lane >> 2);
        if (kn == qt) {
#pragma unroll
            for (int nt = 0; nt < 8; nt++) {
                int c0 = nt * 8 + 2 * (lane & 3);
                float p0 = (c0     <= row0)     ? __expf(sacc[nt][0]) : 0.f;
                float p1 = (c0 + 1 <= row0)     ? __expf(sacc[nt][1]) : 0.f;
                float p2 = (c0     <= row0 + 8) ? __expf(sacc[nt][2]) : 0.f;
                float p3 = (c0 + 1 <= row0 + 8) ? __expf(sacc[nt][3]) : 0.f;
                l0 += p0 + p1; l1 += p2 + p3;
                sacc[nt][0] = p0; sacc[nt][1] = p1;
                sacc[nt][2] = p2; sacc[nt][3] = p3;
            }
        } else {
#pragma unroll
            for (int nt = 0; nt < 8; nt++) {
                float p0 = __expf(sacc[nt][0]);
                float p1 = __expf(sacc[nt][1]);
                float p2 = __expf(sacc[nt][2]);
                float p3 = __expf(sacc[nt][3]);
                l0 += p0 + p1; l1 += p2 + p3;
                sacc[nt][0] = p0; sacc[nt][1] = p1;
                sacc[nt][2] = p2; sacc[nt][3] = p3;
            }
        }

        uint32_t pha[4][4], pla[4][4];
#pragma unroll
        for (int ks = 0; ks < 4; ks++) {
            const float* sA = sacc[2 * ks];
            const float* sB = sacc[2 * ks + 1];
            __nv_bfloat162 h0 = __floats2bfloat162_rn(sA[0], sA[1]);
            __nv_bfloat162 h1 = __floats2bfloat162_rn(sA[2], sA[3]);
            __nv_bfloat162 h2 = __floats2bfloat162_rn(sB[0], sB[1]);
            __nv_bfloat162 h3 = __floats2bfloat162_rn(sB[2], sB[3]);
            pha[ks][0] = *(uint32_t*)&h0; pha[ks][1] = *(uint32_t*)&h1;
            pha[ks][2] = *(uint32_t*)&h2; pha[ks][3] = *(uint32_t*)&h3;
            __nv_bfloat162 e0 = __floats2bfloat162_rn(
                sA[0] - __bfloat162float(h0.x), sA[1] - __bfloat162float(h0.y));
            __nv_bfloat162 e1 = __floats2bfloat162_rn(
                sA[2] - __bfloat162float(h1.x), sA[3] - __bfloat162float(h1.y));
            __nv_bfloat162 e2 = __floats2bfloat162_rn(
                sB[0] - __bfloat162float(h2.x), sB[1] - __bfloat162float(h2.y));
            __nv_bfloat162 e3 = __floats2bfloat162_rn(
                sB[2] - __bfloat162float(h3.x), sB[3] - __bfloat162float(h3.y));
            pla[ks][0] = *(uint32_t*)&e0; pla[ks][1] = *(uint32_t*)&e1;
            pla[ks][2] = *(uint32_t*)&e2; pla[ks][3] = *(uint32_t*)&e3;
        }

        const uint32_t vb = kb + 2 * TILE9;
#pragma unroll
        for (int ks = 0; ks < 4; ks++) {
#pragma unroll
            for (int jp = 0; jp < 4; jp++) {
                uint32_t vfh[4], vfl[4];
                uint32_t addr = vb + vOff + (uint32_t)(ks * 16 * PB) + jp * 32;
                ldsm_x4_t(vfh, addr);
                ldsm_x4_t(vfl, addr + TILE9);
                mma16816(oacc[2 * jp], pha[ks], vfh);
                mma16816(oacc[2 * jp], pla[ks], vfh);
                mma16816(oacc[2 * jp], pha[ks], vfl);
                mma16816(oacc[2 * jp + 1], pha[ks], vfh + 2);
                mma16816(oacc[2 * jp + 1], pla[ks], vfh + 2);
                mma16816(oacc[2 * jp + 1], pha[ks], vfl + 2);
            }
        }
        __syncthreads();
        bsel ^= 1;
    }

    l0 += __shfl_xor_sync(0xffffffffu, l0, 1);
    l0 += __shfl_xor_sync(0xffffffffu, l0, 2);
    l1 += __shfl_xor_sync(0xffffffffu, l1, 1);
    l1 += __shfl_xor_sync(0xffffffffu, l1, 2);
    float i0 = 1.0f / l0, i1 = 1.0f / l1;

    size_t rg0 = (size_t)(b * SEQ + qt * 64 + warp * 16 + (lane >> 2));
    int colb = h * HD + 2 * (lane & 3);
#pragma unroll
    for (int nt = 0; nt < 8; nt++) {
        float a0 = oacc[nt][0] * i0, a1 = oacc[nt][1] * i0;
        float a2 = oacc[nt][2] * i1, a3 = oacc[nt][3] * i1;
        __nv_bfloat162 H0 = __floats2bfloat162_rn(a0, a1);
        __nv_bfloat162 H1 = __floats2bfloat162_rn(a2, a3);
        __nv_bfloat162 L0 = __floats2bfloat162_rn(a0 - __bfloat162float(H0.x),
                                                  a1 - __bfloat162float(H0.y));
        __nv_bfloat162 L1 = __floats2bfloat162_rn(a2 - __bfloat162float(H1.x),
                                                  a3 - __bfloat162float(H1.y));
        size_t off0 = rg0 * QCOLS + colb + nt * 8;
        size_t off1 = (rg0 + 8) * QCOLS + colb + nt * 8;
        *(uint32_t*)(g_oh + off0) = *(uint32_t*)&H0;
        *(uint32_t*)(g_ol + off0) = *(uint32_t*)&L0;
        *(uint32_t*)(g_oh + off1) = *(uint32_t*)&H1;
        *(uint32_t*)(g_ol + off1) = *(uint32_t*)&L1;
    }
}

// ---------------------------------------------------------------------------
extern "C" void kernel_launch(void* const* d_in, const int* in_sizes, int n_in,
                              void* d_out, int out_size) {
    const float* x  = (const float*)d_in[0];
    const float* Wq = (const float*)d_in[1];
    const float* Wk = (const float*)d_in[2];
    const float* Wv = (const float*)d_in[3];
    const float* Wo = (const float*)d_in[4];
    const float* qw = (const float*)d_in[5];
    const float* kw = (const float*)d_in[6];
    float* out = (float*)d_out;

    static int attr_set = 0;
    if (!attr_set) {
        cudaFuncSetAttribute(mm_k, cudaFuncAttributeMaxDynamicSharedMemorySize,
                             MM_SMEM);
        cudaFuncSetAttribute(attn_mma_k,
                             cudaFuncAttributeMaxDynamicSharedMemorySize,
                             ATT_SMEM);
        attr_set = 1;
    }

    // Launches 1-5: prep. Launch 6: mm_k(QKV) -- lands in ncu's -s 5 -c 1 slot.
    split_x_k<<<(MROWS * HID) / (256 * 4), 256>>>(x);
    transpose_split_k<<<dim3(QCOLS / 32, HID / 32), 256>>>(Wq, QCOLS, 0, 2, 3);
    transpose_split_k<<<dim3(KVCOLS / 32, HID / 32), 256>>>(Wk, KVCOLS, 2048, 2, 3);
    transpose_split_k<<<dim3(KVCOLS / 32, HID / 32), 256>>>(Wv, KVCOLS, 2560, 2, 3);
    transpose_split_k<<<dim3(QCOLS / 32, HID / 32), 256>>>(Wo, QCOLS, 0, 8, 9);

    // Fused QKV projection (one GEMM, N=3072); V tiles emit bf16 hi/lo directly
    mm_k<<<dim3(QKVN / 128, MROWS / 128), 256, MM_SMEM>>>(0, 1, 2, 3,
                                                          nullptr, 0, QKVN);

    // RMSNorm + RoPE -> bf16 hi/lo q,k (v already split by mm_k epilogue)
    {
        int nwarps = MROWS * NH + MROWS * NKV;
        rmsnorm_rope_k<<<nwarps / 8, 256>>>(qw, kw);
    }

    // Tensorized causal GQA flash attention -> g_oh / g_ol
    attn_mma_k<<<dim3(SEQ / 64, BATCH * NH), 128, ATT_SMEM>>>();

    // Output projection
    mm_k<<<dim3(QCOLS / 128, MROWS / 128), 256, MM_SMEM>>>(10, 11, 8, 9,
                                                           out, 99, QCOLS);
}